// round 1
// baseline (speedup 1.0000x reference)
#include <cuda_runtime.h>
#include <cstddef>

#define HDIM   512
#define KDIM   1024
#define DPAIR  256
#define NTOK   128
#define NB     4
#define OUTC   774          // 3*(256+2)
#define UVSTRIDE 6144       // 3 mlps * 2 halves * 1024
#define USTRIDE  1028       // padded smem row (breaks bank conflicts)

// scratch: u/v activations for all 3 MLPs: [B*N][mlp][u|v][1024]
__device__ float g_UV[(size_t)NB * NTOK * UVSTRIDE];

// packed fp32x2 FMA (FFMA2) — only reachable via PTX on sm_103a
__device__ __forceinline__ float2 ffma2(float2 a, float2 b, float2 c) {
    float2 d;
    asm("fma.rn.f32x2 %0, %1, %2, %3;"
        : "=l"(*reinterpret_cast<unsigned long long*>(&d))
        : "l"(*reinterpret_cast<const unsigned long long*>(&a)),
          "l"(*reinterpret_cast<const unsigned long long*>(&b)),
          "l"(*reinterpret_cast<const unsigned long long*>(&c)));
    return d;
}

// ---------------------------------------------------------------------------
// Kernel 1: UV = P @ [W1f_top|W1f_bot|W1h1_top|...]  -> [512 rows, 6144 cols]
// Tiled 64x64, BK=16, 256 threads, 4x4 microtile.
// ---------------------------------------------------------------------------
__global__ __launch_bounds__(256, 2) void uv_gemm(
    const float* __restrict__ P,
    const float* __restrict__ W1_0,
    const float* __restrict__ W1_1,
    const float* __restrict__ W1_2)
{
    __shared__ float As[16][68];
    __shared__ float Bs[16][64];

    const int rb = blockIdx.y << 6;                 // row block (0..448)
    const int cb = blockIdx.x << 6;                 // col block (0..6080)
    const int m      = cb >> 11;                    // which MLP (2048 cols each)
    const int within = cb & 2047;
    const int half   = within >> 10;                // 0 = u (rows 0..511), 1 = v
    const int ccb    = within & 1023;
    const float* W1 = (m == 0) ? W1_0 : ((m == 1) ? W1_1 : W1_2);
    const float* Bb = W1 + (size_t)(half * 512) * 1024 + ccb;

    const int tid = threadIdx.x;
    const int tx = tid & 15, ty = tid >> 4;
    const int arn = tid >> 2, akk = (tid & 3) << 2;
    const int bkk = tid >> 4, bcn = (tid & 15) << 2;

    float acc[4][4] = {};

    for (int k0 = 0; k0 < HDIM; k0 += 16) {
        float4 a = *(const float4*)(P + (size_t)(rb + arn) * HDIM + k0 + akk);
        As[akk + 0][arn] = a.x;
        As[akk + 1][arn] = a.y;
        As[akk + 2][arn] = a.z;
        As[akk + 3][arn] = a.w;
        *(float4*)&Bs[bkk][bcn] =
            *(const float4*)(Bb + (size_t)(k0 + bkk) * 1024 + bcn);
        __syncthreads();

        #pragma unroll
        for (int kk = 0; kk < 16; kk++) {
            float av[4], bv[4];
            #pragma unroll
            for (int i = 0; i < 4; i++) av[i] = As[kk][ty * 4 + i];
            #pragma unroll
            for (int j = 0; j < 4; j++) bv[j] = Bs[kk][tx * 4 + j];
            #pragma unroll
            for (int i = 0; i < 4; i++)
                #pragma unroll
                for (int j = 0; j < 4; j++)
                    acc[i][j] = fmaf(av[i], bv[j], acc[i][j]);
        }
        __syncthreads();
    }

    #pragma unroll
    for (int i = 0; i < 4; i++) {
        float4 v = make_float4(acc[i][0], acc[i][1], acc[i][2], acc[i][3]);
        *(float4*)(g_UV + (size_t)(rb + ty * 4 + i) * UVSTRIDE + cb + tx * 4) = v;
    }
}

// ---------------------------------------------------------------------------
// Kernel 2: fused pair MLP + head + softmax.
// Block = (b, m, i-tile of 8, j-tile of 8) -> 64 z-rows x 256 output cols.
// 256 threads: warp tr owns row-i = it*8+tr, lanes tc own 4 col-pairs each.
// z chunk (relu(u_i+v_j), duplicated to {z,z}) built in SMEM per K=16 step;
// inner product uses packed FFMA2.
// ---------------------------------------------------------------------------
__global__ __launch_bounds__(256, 1) void pair_kernel(
    const float* __restrict__ W2_0, const float* __restrict__ W2_1,
    const float* __restrict__ W2_2,
    const float* __restrict__ w3_0, const float* __restrict__ w3_1,
    const float* __restrict__ w3_2,
    float* __restrict__ out)
{
    extern __shared__ float sm[];
    float*  us  = sm;                         // 8 * 1028
    float*  vs  = us + 8 * USTRIDE;           // 8 * 1028
    float*  ws  = vs + 8 * USTRIDE;           // 16 * 256 (W2 chunk, row-major)
    float2* zs2 = (float2*)(ws + 16 * DPAIR); // 16 * 64  ({z,z} duplicated)

    const int jt = blockIdx.x;
    const int it = blockIdx.y;
    const int bz = blockIdx.z;
    const int b = bz / 3, m = bz - b * 3;
    const float* W2 = (m == 0) ? W2_0 : ((m == 1) ? W2_1 : W2_2);
    const float* w3 = (m == 0) ? w3_0 : ((m == 1) ? w3_1 : w3_2);

    const int tid = threadIdx.x;
    const int tc = tid & 31;   // lane -> column pairs {tc+32*pp}
    const int tr = tid >> 5;   // warp -> local i row

    // preload u (8 i-rows) and v (8 j-rows) tiles, K=1024 each
    const float* Ubase = g_UV + (size_t)(b * NTOK + it * 8) * UVSTRIDE + m * 2048;
    const float* Vbase = g_UV + (size_t)(b * NTOK + jt * 8) * UVSTRIDE + m * 2048 + 1024;
    for (int idx = tid; idx < 2048; idx += 256) {
        int r = idx >> 8, c4 = (idx & 255) << 2;
        *(float4*)(us + r * USTRIDE + c4) =
            *(const float4*)(Ubase + (size_t)r * UVSTRIDE + c4);
        *(float4*)(vs + r * USTRIDE + c4) =
            *(const float4*)(Vbase + (size_t)r * UVSTRIDE + c4);
    }
    __syncthreads();

    float2 acc[8][4];
    #pragma unroll
    for (int q = 0; q < 8; q++)
        #pragma unroll
        for (int pp = 0; pp < 4; pp++) acc[q][pp] = make_float2(0.f, 0.f);

    for (int k0 = 0; k0 < KDIM; k0 += 16) {
        // stream W2 chunk (16 rows x 256 = one contiguous 4096-float slab)
        #pragma unroll
        for (int t = 0; t < 4; t++) {
            int idx4 = tid + t * 256;
            *(float4*)(ws + idx4 * 4) =
                *(const float4*)(W2 + (size_t)k0 * DPAIR + idx4 * 4);
        }
        // build z chunk: zs2[kk][r] = {z, z}, z = relu(u[i(r),k0+kk]+v[j(r),k0+kk])
        #pragma unroll
        for (int t = 0; t < 4; t++) {
            int idx = tid + t * 256;
            int kk = idx >> 6, r = idx & 63;
            float z = us[(r >> 3) * USTRIDE + k0 + kk] +
                      vs[(r & 7) * USTRIDE + k0 + kk];
            z = fmaxf(z, 0.f);
            zs2[kk * 64 + r] = make_float2(z, z);
        }
        __syncthreads();

        #pragma unroll
        for (int kk = 0; kk < 16; kk++) {
            // 8 duplicated z values for this warp's 8 rows (broadcast LDS.128)
            const float4* zp = (const float4*)(zs2 + kk * 64 + tr * 8);
            float4 za = zp[0], zb = zp[1], zc = zp[2], zd = zp[3];
            float2 zf[8];
            zf[0] = make_float2(za.x, za.y); zf[1] = make_float2(za.z, za.w);
            zf[2] = make_float2(zb.x, zb.y); zf[3] = make_float2(zb.z, zb.w);
            zf[4] = make_float2(zc.x, zc.y); zf[5] = make_float2(zc.z, zc.w);
            zf[6] = make_float2(zd.x, zd.y); zf[7] = make_float2(zd.z, zd.w);
            // 4 W2 column-pairs for this lane (conflict-free LDS.64)
            const float2* wp = (const float2*)ws + kk * 128 + tc;
            float2 wf[4];
            #pragma unroll
            for (int pp = 0; pp < 4; pp++) wf[pp] = wp[pp * 32];
            #pragma unroll
            for (int q = 0; q < 8; q++)
                #pragma unroll
                for (int pp = 0; pp < 4; pp++)
                    acc[q][pp] = ffma2(zf[q], wf[pp], acc[q][pp]);
        }
        __syncthreads();
    }

    // epilogue: relu, head logits, warp-reduce, softmax, store
    float4 w3v[4];
    #pragma unroll
    for (int pp = 0; pp < 4; pp++)
        w3v[pp] = *(const float4*)(w3 + 4 * (tc + 32 * pp));

    const int i = it * 8 + tr;
    #pragma unroll
    for (int q = 0; q < 8; q++) {
        float l0 = 0.f, l1 = 0.f;
        #pragma unroll
        for (int pp = 0; pp < 4; pp++) {
            float2 a = acc[q][pp];
            a.x = fmaxf(a.x, 0.f);
            a.y = fmaxf(a.y, 0.f);
            acc[q][pp] = a;
            l0 += a.x * w3v[pp].x + a.y * w3v[pp].z;
            l1 += a.x * w3v[pp].y + a.y * w3v[pp].w;
        }
        #pragma unroll
        for (int off = 16; off; off >>= 1) {
            l0 += __shfl_xor_sync(0xffffffffu, l0, off);
            l1 += __shfl_xor_sync(0xffffffffu, l1, off);
        }
        const int j = jt * 8 + q;
        float* orow = out + (size_t)((b * NTOK + i) * NTOK + j) * OUTC + m * 258;
        #pragma unroll
        for (int pp = 0; pp < 4; pp++)
            *(float2*)(orow + 2 * tc + 64 * pp) = acc[q][pp];
        if (tc == 0) {
            float mx = fmaxf(l0, l1);
            float e0 = expf(l0 - mx), e1 = expf(l1 - mx);
            float inv = 1.f / (e0 + e1);
            *(float2*)(orow + 256) = make_float2(e0 * inv, e1 * inv);
        }
    }
}

// ---------------------------------------------------------------------------
#define PAIR_SMEM_BYTES ((8 * USTRIDE * 2 + 16 * DPAIR + 16 * 64 * 2) * 4)

extern "C" void kernel_launch(void* const* d_in, const int* in_sizes, int n_in,
                              void* d_out, int out_size) {
    (void)in_sizes; (void)n_in; (void)out_size;
    const float* P    = (const float*)d_in[0];
    const float* Wf1  = (const float*)d_in[1];
    const float* Wf2  = (const float*)d_in[2];
    const float* w3   = (const float*)d_in[3];
    const float* Wh1a = (const float*)d_in[4];
    const float* Wh1b = (const float*)d_in[5];
    const float* wl1  = (const float*)d_in[6];
    const float* Wh2a = (const float*)d_in[7];
    const float* Wh2b = (const float*)d_in[8];
    const float* wl2  = (const float*)d_in[9];
    float* out = (float*)d_out;

    cudaFuncSetAttribute(pair_kernel,
                         cudaFuncAttributeMaxDynamicSharedMemorySize,
                         PAIR_SMEM_BYTES);

    // UV = P @ [all W1 halves]: grid 96 col-blocks x 8 row-blocks
    uv_gemm<<<dim3(96, 8), 256>>>(P, Wf1, Wh1a, Wh2a);

    // fused pair MLPs: 16 j-tiles x 16 i-tiles x (4 batches * 3 mlps)
    pair_kernel<<<dim3(16, 16, 12), 256, PAIR_SMEM_BYTES>>>(
        Wf2, Wh1b, Wh2b, w3, wl1, wl2, out);
}

// round 3
// speedup vs baseline: 3.2624x; 3.2624x over previous
#include <cuda_runtime.h>
#include <cstdint>
#include <cstddef>

#define HDIM   512
#define KDIM   1024
#define DPAIR  256
#define NTOK   128
#define OUTC   774
#define UVSTRIDE 6144
#define KC     32
#define NCH    32            // 1024 / 32

// device scratch (no allocs allowed)
__device__ float g_UV[(size_t)4 * NTOK * UVSTRIDE];          // u/v activations (k-permuted)
__device__ float g_W2R[(size_t)3 * NCH * DPAIR * KC];        // W2 packed [m][c][n][32], tf32

// ---------------- smem layout (bytes) ----------------
#define WS_STRIDE 160                          // bytes per n-row (20 float2; %32w == 8)
#define STAGE_BYTES (DPAIR * WS_STRIDE + 16 * 128 + 8 * 160)   // 40960+2048+1280 = 44288
#define WS_OFF(s) ((s) * STAGE_BYTES)
#define US_OFF(s) (WS_OFF(s) + DPAIR * WS_STRIDE)
#define VS_OFF(s) (US_OFF(s) + 16 * 128)
#define W3_OFF    (2 * STAGE_BYTES)            // 88576, 2048 B
#define LOG_OFF   (W3_OFF + 2048)              // [128 rows][4 wn][2] floats = 4096 B
#define SMEM_TOTAL (LOG_OFF + 4096)            // 94720

// ---------------- helpers ----------------
__device__ __forceinline__ uint32_t cv_tf32(float x) {       // rna round, u32 container
    uint32_t r;
    asm("cvt.rna.tf32.f32 %0, %1;" : "=r"(r) : "f"(x));
    return r;
}
__device__ __forceinline__ float cv_tf32f(float x) {
    return __uint_as_float(cv_tf32(x));
}
__device__ __forceinline__ void mma_tf32(float* c, const uint32_t* a,
                                         uint32_t b0, uint32_t b1) {
    asm volatile(
        "mma.sync.aligned.m16n8k8.row.col.f32.tf32.tf32.f32 "
        "{%0,%1,%2,%3}, {%4,%5,%6,%7}, {%8,%9}, {%0,%1,%2,%3};"
        : "+f"(c[0]), "+f"(c[1]), "+f"(c[2]), "+f"(c[3])
        : "r"(a[0]), "r"(a[1]), "r"(a[2]), "r"(a[3]), "r"(b0), "r"(b1));
}

// ---------------------------------------------------------------------------
// Kernel A: UV = P @ [W1 halves] -> g_UV [512, 6144], k permuted within 8-blocks
// so that u/v chunk rows are directly fragment-ordered: k -> (k&~7)|((k&3)<<1)|((k&4)>>2)
// ---------------------------------------------------------------------------
__global__ __launch_bounds__(256, 2) void uv_gemm(
    const float* __restrict__ P,
    const float* __restrict__ W1_0,
    const float* __restrict__ W1_1,
    const float* __restrict__ W1_2)
{
    __shared__ float As[16][68];
    __shared__ float Bs[16][64];

    const int rb = blockIdx.y << 6;
    const int cb = blockIdx.x << 6;
    const int m      = cb >> 11;
    const int within = cb & 2047;
    const int half   = within >> 10;
    const int ccb    = within & 1023;
    const float* W1 = (m == 0) ? W1_0 : ((m == 1) ? W1_1 : W1_2);
    const float* Bb = W1 + (size_t)(half * 512) * 1024 + ccb;

    const int tid = threadIdx.x;
    const int tx = tid & 15, ty = tid >> 4;
    const int arn = tid >> 2, akk = (tid & 3) << 2;
    const int bkk = tid >> 4, bcn = (tid & 15) << 2;

    float acc[4][4] = {};

    for (int k0 = 0; k0 < HDIM; k0 += 16) {
        float4 a = *(const float4*)(P + (size_t)(rb + arn) * HDIM + k0 + akk);
        As[akk + 0][arn] = a.x;
        As[akk + 1][arn] = a.y;
        As[akk + 2][arn] = a.z;
        As[akk + 3][arn] = a.w;
        *(float4*)&Bs[bkk][bcn] =
            *(const float4*)(Bb + (size_t)(k0 + bkk) * 1024 + bcn);
        __syncthreads();

        #pragma unroll
        for (int kk = 0; kk < 16; kk++) {
            float av[4], bv[4];
            #pragma unroll
            for (int i = 0; i < 4; i++) av[i] = As[kk][ty * 4 + i];
            #pragma unroll
            for (int j = 0; j < 4; j++) bv[j] = Bs[kk][tx * 4 + j];
            #pragma unroll
            for (int i = 0; i < 4; i++)
                #pragma unroll
                for (int j = 0; j < 4; j++)
                    acc[i][j] = fmaf(av[i], bv[j], acc[i][j]);
        }
        __syncthreads();
    }

    // permuted scalar stores: k = cb + tx*4 + jj
    const int colbase = cb + ((tx >> 1) << 3) + (tx & 1);
    #pragma unroll
    for (int i = 0; i < 4; i++) {
        float* row = g_UV + (size_t)(rb + ty * 4 + i) * UVSTRIDE;
        #pragma unroll
        for (int jj = 0; jj < 4; jj++)
            row[colbase + (jj << 1)] = acc[i][jj];
    }
}

// ---------------------------------------------------------------------------
// Kernel B: pack W2 [1024,256] -> g_W2R [m][c][n][32], tf32-rounded, frag order
// ---------------------------------------------------------------------------
__global__ void w2_pack(const float* __restrict__ W2_0,
                        const float* __restrict__ W2_1,
                        const float* __restrict__ W2_2)
{
    const int c = blockIdx.x, m = blockIdx.y;
    const int n = threadIdx.x;
    const float* W2 = (m == 0) ? W2_0 : ((m == 1) ? W2_1 : W2_2);
    float* dst = g_W2R + (((size_t)m * NCH + c) * DPAIR + n) * KC;
    #pragma unroll
    for (int kk = 0; kk < 32; kk++) {
        float v = W2[(size_t)(c * 32 + kk) * DPAIR + n];
        int p = (kk >> 3) * 4 + (kk & 3);
        int comp = (kk >> 2) & 1;
        dst[p * 2 + comp] = cv_tf32f(v);
    }
}

// ---------------------------------------------------------------------------
// Kernel C: HMMA tf32 pair MLP + head + softmax.
// CTA: 128 pair-rows (16 i x 8 j) x 256 cols, K=1024, double-buffered KC=32.
// 8 warps, warp tile 64x64 (wm: rows, wn: cols).
// ---------------------------------------------------------------------------
__global__ __launch_bounds__(256) void pair_mma(
    const float* __restrict__ w3_0, const float* __restrict__ w3_1,
    const float* __restrict__ w3_2, float* __restrict__ out)
{
    extern __shared__ char sm[];
    const int tid = threadIdx.x;
    const int l = tid & 31, wid = tid >> 5;
    const int qid = l >> 2, qpos = l & 3;
    const int wm = wid >> 2, wn = wid & 3;

    const int jt = blockIdx.x;     // 16 -> 8 j rows
    const int it = blockIdx.y;     // 8  -> 16 i rows
    const int bz = blockIdx.z;     // 12
    const int b = bz / 3, m = bz % 3;

    const float* w3 = (m == 0) ? w3_0 : ((m == 1) ? w3_1 : w3_2);
    if (tid < 128)
        ((float4*)(sm + W3_OFF))[tid] = ((const float4*)w3)[tid];

    const float* W2base = g_W2R + (size_t)m * NCH * DPAIR * KC;
    const float* Ubase = g_UV + (size_t)(b * NTOK + it * 16) * UVSTRIDE + m * 2048;
    const float* Vbase = g_UV + (size_t)(b * NTOK + jt * 8) * UVSTRIDE + m * 2048 + 1024;

    float acc[4][8][4];
    #pragma unroll
    for (int t = 0; t < 4; t++)
        #pragma unroll
        for (int nt = 0; nt < 8; nt++)
            #pragma unroll
            for (int cc = 0; cc < 4; cc++) acc[t][nt][cc] = 0.f;

    // prefetch chunk 0
    float4 rw[8];
    float4 ru = make_float4(0.f, 0.f, 0.f, 0.f);
    {
        const float* wp = W2base;
        #pragma unroll
        for (int q = 0; q < 8; q++)
            rw[q] = *(const float4*)(wp + (size_t)(q * 256 + tid) * 4);
        if (tid < 128)
            ru = *(const float4*)(Ubase + (size_t)(tid >> 3) * UVSTRIDE + (tid & 7) * 4);
        else if (tid < 192)
            ru = *(const float4*)(Vbase + (size_t)((tid - 128) >> 3) * UVSTRIDE + (tid & 7) * 4);
    }

    for (int c = 0; c < NCH; c++) {
        const int s = c & 1;
        char* ws = sm + WS_OFF(s);
        char* us = sm + US_OFF(s);
        char* vs = sm + VS_OFF(s);

        // stores into stage s
        #pragma unroll
        for (int q = 0; q < 8; q++) {
            int fi = q * 256 + tid;
            int n = fi >> 3, j = fi & 7;
            *(float4*)(ws + n * WS_STRIDE + j * 16) = rw[q];
        }
        if (tid < 128)
            *(float4*)(us + (tid >> 3) * 128 + (tid & 7) * 16) = ru;
        else if (tid < 192)
            *(float4*)(vs + ((tid - 128) >> 3) * 160 + (tid & 7) * 16) = ru;
        __syncthreads();

        // prefetch next chunk (latency hidden under MMA below)
        if (c + 1 < NCH) {
            const float* wp = W2base + (size_t)(c + 1) * DPAIR * KC;
            #pragma unroll
            for (int q = 0; q < 8; q++)
                rw[q] = *(const float4*)(wp + (size_t)(q * 256 + tid) * 4);
            if (tid < 128)
                ru = *(const float4*)(Ubase + (size_t)(tid >> 3) * UVSTRIDE +
                                      (c + 1) * 32 + (tid & 7) * 4);
            else if (tid < 192)
                ru = *(const float4*)(Vbase + (size_t)((tid - 128) >> 3) * UVSTRIDE +
                                      (c + 1) * 32 + (tid & 7) * 4);
        }

        // 4 k-steps of m16n8k8
        #pragma unroll
        for (int ks = 0; ks < 4; ks++) {
            const int po = (ks * 4 + qpos) * 8;               // byte offset of float2
            float2 v2 = *(const float2*)(vs + qid * 160 + po);
            uint32_t a[4][4];
            #pragma unroll
            for (int t = 0; t < 4; t++) {
                float2 u0 = *(const float2*)(us + (wm * 8 + 2 * t) * 128 + po);
                float2 u1 = *(const float2*)(us + (wm * 8 + 2 * t + 1) * 128 + po);
                a[t][0] = cv_tf32(fmaxf(u0.x + v2.x, 0.f));
                a[t][1] = cv_tf32(fmaxf(u1.x + v2.x, 0.f));
                a[t][2] = cv_tf32(fmaxf(u0.y + v2.y, 0.f));
                a[t][3] = cv_tf32(fmaxf(u1.y + v2.y, 0.f));
            }
            #pragma unroll
            for (int nt = 0; nt < 8; nt++) {
                float2 bv = *(const float2*)(ws + (wn * 64 + nt * 8 + qid) * WS_STRIDE + po);
                uint32_t b0 = __float_as_uint(bv.x);
                uint32_t b1 = __float_as_uint(bv.y);
                #pragma unroll
                for (int t = 0; t < 4; t++)
                    mma_tf32(acc[t][nt], a[t], b0, b1);
            }
        }
    }

    // ---------------- epilogue ----------------
    const float* w3s = (const float*)(sm + W3_OFF);
    float* logp = (float*)(sm + LOG_OFF);
    const int j_g = jt * 8 + qid;

    #pragma unroll
    for (int t = 0; t < 4; t++) {
        #pragma unroll
        for (int half = 0; half < 2; half++) {
            const int i_g = it * 16 + wm * 8 + 2 * t + half;
            float* orow = out + (size_t)((b * NTOK + i_g) * NTOK + j_g) * OUTC
                        + m * 258 + wn * 64;
            float l0 = 0.f, l1 = 0.f;
            #pragma unroll
            for (int nt = 0; nt < 8; nt++) {
                float d0 = fmaxf(acc[t][nt][half * 2],     0.f);
                float d1 = fmaxf(acc[t][nt][half * 2 + 1], 0.f);
                int nn = nt * 8 + qpos * 2;
                float4 wv = *(const float4*)(w3s + (wn * 64 + nn) * 2);
                l0 = fmaf(d0, wv.x, fmaf(d1, wv.z, l0));
                l1 = fmaf(d0, wv.y, fmaf(d1, wv.w, l1));
                *(float2*)(orow + nn) = make_float2(d0, d1);
            }
            // reduce over qpos (lanes sharing a row)
            l0 += __shfl_xor_sync(0xffffffffu, l0, 1);
            l1 += __shfl_xor_sync(0xffffffffu, l1, 1);
            l0 += __shfl_xor_sync(0xffffffffu, l0, 2);
            l1 += __shfl_xor_sync(0xffffffffu, l1, 2);
            if (qpos == 0) {
                int r_cta = wm * 64 + t * 16 + half * 8 + qid;
                *(float2*)(logp + r_cta * 8 + wn * 2) = make_float2(l0, l1);
            }
        }
    }
    __syncthreads();

    if (tid < 128) {
        float l0 = 0.f, l1 = 0.f;
        #pragma unroll
        for (int w = 0; w < 4; w++) {
            float2 p = *(const float2*)(logp + tid * 8 + w * 2);
            l0 += p.x; l1 += p.y;
        }
        float mx = fmaxf(l0, l1);
        float e0 = __expf(l0 - mx), e1 = __expf(l1 - mx);
        float inv = 1.f / (e0 + e1);
        const int i_g = it * 16 + (tid >> 3);
        const int jg2 = jt * 8 + (tid & 7);
        float* orow = out + (size_t)((b * NTOK + i_g) * NTOK + jg2) * OUTC + m * 258;
        *(float2*)(orow + 256) = make_float2(e0 * inv, e1 * inv);
    }
}

// ---------------------------------------------------------------------------
extern "C" void kernel_launch(void* const* d_in, const int* in_sizes, int n_in,
                              void* d_out, int out_size) {
    (void)in_sizes; (void)n_in; (void)out_size;
    const float* P    = (const float*)d_in[0];
    const float* Wf1  = (const float*)d_in[1];
    const float* Wf2  = (const float*)d_in[2];
    const float* w3   = (const float*)d_in[3];
    const float* Wh1a = (const float*)d_in[4];
    const float* Wh1b = (const float*)d_in[5];
    const float* wl1  = (const float*)d_in[6];
    const float* Wh2a = (const float*)d_in[7];
    const float* Wh2b = (const float*)d_in[8];
    const float* wl2  = (const float*)d_in[9];
    float* out = (float*)d_out;

    cudaFuncSetAttribute(pair_mma,
                         cudaFuncAttributeMaxDynamicSharedMemorySize,
                         SMEM_TOTAL);

    w2_pack<<<dim3(NCH, 3), 256>>>(Wf2, Wh1b, Wh2b);
    uv_gemm<<<dim3(96, 8), 256>>>(P, Wf1, Wh1a, Wh2a);
    pair_mma<<<dim3(16, 8, 12), 256, SMEM_TOTAL>>>(w3, wl1, wl2, out);
}

// round 4
// speedup vs baseline: 3.3692x; 1.0327x over previous
#include <cuda_runtime.h>
#include <cstdint>
#include <cstddef>

#define HDIM   512
#define KDIM   1024
#define DPAIR  256
#define NTOK   128
#define OUTC   774
#define UVSTRIDE 6144
#define KC     32
#define NCH    32            // 1024 / 32

// device scratch (no allocs allowed)
__device__ float g_UV[(size_t)4 * NTOK * UVSTRIDE];          // u/v activations (k-permuted)
__device__ float g_W2R[(size_t)3 * NCH * DPAIR * KC];        // W2 packed [m][c][n][32], tf32

// ---------------- smem layout (bytes) ----------------
#define U_STRIDE  4112                 // 1028 floats per row (16B aligned, bank-skewed)
#define WS_STRIDE 160                  // bytes per n-row of a W2 chunk
#define US_OFF    0                    // 16 rows  -> 65792
#define VS_OFF    65792                // 8 rows   -> 32896
#define WS_OFF(s) (98688 + (s) * (DPAIR * WS_STRIDE))   // 2 x 40960
#define W3_OFF    180608               // 2048
#define LOG_OFF   182656               // 128 rows x 4 wn x 2 floats = 4096
#define SMEM_TOTAL 186752

// ---------------- helpers ----------------
__device__ __forceinline__ uint32_t smem_u32(const void* p) {
    uint32_t a;
    asm("{ .reg .u64 t; cvta.to.shared.u64 t, %1; cvt.u32.u64 %0, t; }"
        : "=r"(a) : "l"(p));
    return a;
}
__device__ __forceinline__ void cp16(uint32_t dst, const void* src) {
    asm volatile("cp.async.cg.shared.global [%0], [%1], 16;"
                 :: "r"(dst), "l"(src));
}
__device__ __forceinline__ void cp_commit() {
    asm volatile("cp.async.commit_group;" ::: "memory");
}
__device__ __forceinline__ void cp_wait0() {
    asm volatile("cp.async.wait_group 0;" ::: "memory");
}
__device__ __forceinline__ uint32_t cv_tf32(float x) {       // rna round, u32 container
    uint32_t r;
    asm("cvt.rna.tf32.f32 %0, %1;" : "=r"(r) : "f"(x));
    return r;
}
__device__ __forceinline__ float cv_tf32f(float x) {
    return __uint_as_float(cv_tf32(x));
}
__device__ __forceinline__ void mma_tf32(float* c, const uint32_t* a,
                                         uint32_t b0, uint32_t b1) {
    asm volatile(
        "mma.sync.aligned.m16n8k8.row.col.f32.tf32.tf32.f32 "
        "{%0,%1,%2,%3}, {%4,%5,%6,%7}, {%8,%9}, {%0,%1,%2,%3};"
        : "+f"(c[0]), "+f"(c[1]), "+f"(c[2]), "+f"(c[3])
        : "r"(a[0]), "r"(a[1]), "r"(a[2]), "r"(a[3]), "r"(b0), "r"(b1));
}

// ---------------------------------------------------------------------------
// Kernel A: UV = P @ [W1 halves] -> g_UV [512, 6144], k permuted within 8-blocks
// (k -> (k&~7)|((k&3)<<1)|((k&4)>>2)) so fragment k-pairs are float2-adjacent.
// ---------------------------------------------------------------------------
__global__ __launch_bounds__(256, 2) void uv_gemm(
    const float* __restrict__ P,
    const float* __restrict__ W1_0,
    const float* __restrict__ W1_1,
    const float* __restrict__ W1_2)
{
    __shared__ float As[16][68];
    __shared__ float Bs[16][64];

    const int rb = blockIdx.y << 6;
    const int cb = blockIdx.x << 6;
    const int m      = cb >> 11;
    const int within = cb & 2047;
    const int half   = within >> 10;
    const int ccb    = within & 1023;
    const float* W1 = (m == 0) ? W1_0 : ((m == 1) ? W1_1 : W1_2);
    const float* Bb = W1 + (size_t)(half * 512) * 1024 + ccb;

    const int tid = threadIdx.x;
    const int tx = tid & 15, ty = tid >> 4;
    const int arn = tid >> 2, akk = (tid & 3) << 2;
    const int bkk = tid >> 4, bcn = (tid & 15) << 2;

    float acc[4][4] = {};

    for (int k0 = 0; k0 < HDIM; k0 += 16) {
        float4 a = *(const float4*)(P + (size_t)(rb + arn) * HDIM + k0 + akk);
        As[akk + 0][arn] = a.x;
        As[akk + 1][arn] = a.y;
        As[akk + 2][arn] = a.z;
        As[akk + 3][arn] = a.w;
        *(float4*)&Bs[bkk][bcn] =
            *(const float4*)(Bb + (size_t)(k0 + bkk) * 1024 + bcn);
        __syncthreads();

        #pragma unroll
        for (int kk = 0; kk < 16; kk++) {
            float av[4], bv[4];
            #pragma unroll
            for (int i = 0; i < 4; i++) av[i] = As[kk][ty * 4 + i];
            #pragma unroll
            for (int j = 0; j < 4; j++) bv[j] = Bs[kk][tx * 4 + j];
            #pragma unroll
            for (int i = 0; i < 4; i++)
                #pragma unroll
                for (int j = 0; j < 4; j++)
                    acc[i][j] = fmaf(av[i], bv[j], acc[i][j]);
        }
        __syncthreads();
    }

    const int colbase = cb + ((tx >> 1) << 3) + (tx & 1);
    #pragma unroll
    for (int i = 0; i < 4; i++) {
        float* row = g_UV + (size_t)(rb + ty * 4 + i) * UVSTRIDE;
        #pragma unroll
        for (int jj = 0; jj < 4; jj++)
            row[colbase + (jj << 1)] = acc[i][jj];
    }
}

// ---------------------------------------------------------------------------
// Kernel B: pack W2 [1024,256] -> g_W2R [m][c][n][32], tf32-rounded, frag order
// ---------------------------------------------------------------------------
__global__ void w2_pack(const float* __restrict__ W2_0,
                        const float* __restrict__ W2_1,
                        const float* __restrict__ W2_2)
{
    const int c = blockIdx.x, m = blockIdx.y;
    const int n = threadIdx.x;
    const float* W2 = (m == 0) ? W2_0 : ((m == 1) ? W2_1 : W2_2);
    float* dst = g_W2R + (((size_t)m * NCH + c) * DPAIR + n) * KC;
    #pragma unroll
    for (int kk = 0; kk < 32; kk++) {
        float v = W2[(size_t)(c * 32 + kk) * DPAIR + n];
        int p = (kk >> 3) * 4 + (kk & 3);
        int comp = (kk >> 2) & 1;
        dst[p * 2 + comp] = cv_tf32f(v);
    }
}

// ---------------------------------------------------------------------------
// Kernel C: HMMA tf32 pair MLP + head + softmax. 512 threads, 16 warps (4m x 4n).
// CTA tile 128 pair-rows x 256 cols; warp tile 32x64; acc = 64 regs.
// u/v resident in SMEM for full K; W2 double-buffered via cp.async.
// ---------------------------------------------------------------------------
__global__ __launch_bounds__(512, 1) void pair_mma(
    const float* __restrict__ w3_0, const float* __restrict__ w3_1,
    const float* __restrict__ w3_2, float* __restrict__ out)
{
    extern __shared__ char sm[];
    const uint32_t sb = smem_u32(sm);
    const int tid = threadIdx.x;
    const int l = tid & 31, wid = tid >> 5;
    const int qid = l >> 2, qpos = l & 3;
    const int wm = wid >> 2, wn = wid & 3;

    const int jt = blockIdx.x;     // 16 -> 8 j rows
    const int it = blockIdx.y;     // 8  -> 16 i rows
    const int bz = blockIdx.z;     // 12
    const int b = bz / 3, m = bz % 3;

    const float* w3 = (m == 0) ? w3_0 : ((m == 1) ? w3_1 : w3_2);
    if (tid < 128)
        ((float4*)(sm + W3_OFF))[tid] = ((const float4*)w3)[tid];

    const char* W2base = (const char*)(g_W2R + (size_t)m * NCH * DPAIR * KC);
    const char* Ubase = (const char*)(g_UV + (size_t)(b * NTOK + it * 16) * UVSTRIDE + m * 2048);
    const char* Vbase = (const char*)(g_UV + (size_t)(b * NTOK + jt * 8) * UVSTRIDE + m * 2048 + 1024);

    // ---- prologue: resident u/v (6144 x16B) + W2 chunk 0 (2048 x16B) ----
    #pragma unroll
    for (int q = 0; q < 8; q++) {              // u: 4096 units
        int idx = q * 512 + tid;
        int r = idx >> 8, c16 = idx & 255;
        cp16(sb + US_OFF + r * U_STRIDE + c16 * 16,
             Ubase + (size_t)r * (UVSTRIDE * 4) + c16 * 16);
    }
    #pragma unroll
    for (int q = 0; q < 4; q++) {              // v: 2048 units
        int idx = q * 512 + tid;
        int r = idx >> 8, c16 = idx & 255;
        cp16(sb + VS_OFF + r * U_STRIDE + c16 * 16,
             Vbase + (size_t)r * (UVSTRIDE * 4) + c16 * 16);
    }
    #pragma unroll
    for (int q = 0; q < 4; q++) {              // W2 chunk 0
        int fi = q * 512 + tid;
        int n = fi >> 3, part = fi & 7;
        cp16(sb + WS_OFF(0) + n * WS_STRIDE + part * 16,
             W2base + (size_t)fi * 16);
    }
    cp_commit();
    cp_wait0();
    __syncthreads();

    float acc[2][8][4];
    #pragma unroll
    for (int t = 0; t < 2; t++)
        #pragma unroll
        for (int nt = 0; nt < 8; nt++)
            #pragma unroll
            for (int cc = 0; cc < 4; cc++) acc[t][nt][cc] = 0.f;

    const uint32_t u_base = sb + US_OFF + (wm * 4) * U_STRIDE;
    const uint32_t v_base = sb + VS_OFF + qid * U_STRIDE;

    for (int c = 0; c < NCH; c++) {
        const int s = c & 1;
        const uint32_t ws = sb + WS_OFF(s);
        const uint32_t cb128 = c * 128;

        // issue next W2 chunk into the other stage (stage free: previous sync)
        if (c + 1 < NCH) {
            const char* wp = W2base + (size_t)(c + 1) * (DPAIR * KC * 4);
            #pragma unroll
            for (int q = 0; q < 4; q++) {
                int fi = q * 512 + tid;
                int n = fi >> 3, part = fi & 7;
                cp16(sb + WS_OFF(s ^ 1) + n * WS_STRIDE + part * 16,
                     wp + (size_t)fi * 16);
            }
            cp_commit();
        }

        // 4 k-steps of m16n8k8
        #pragma unroll
        for (int ks = 0; ks < 4; ks++) {
            const uint32_t po = cb128 + (ks * 4 + qpos) * 8;
            float2 v2 = *(const float2*)(sm + (v_base - sb) + po);
            uint32_t a[2][4];
            #pragma unroll
            for (int t = 0; t < 2; t++) {
                float2 u0 = *(const float2*)(sm + (u_base - sb) + (t * 2) * U_STRIDE + po);
                float2 u1 = *(const float2*)(sm + (u_base - sb) + (t * 2 + 1) * U_STRIDE + po);
                a[t][0] = cv_tf32(fmaxf(u0.x + v2.x, 0.f));
                a[t][1] = cv_tf32(fmaxf(u1.x + v2.x, 0.f));
                a[t][2] = cv_tf32(fmaxf(u0.y + v2.y, 0.f));
                a[t][3] = cv_tf32(fmaxf(u1.y + v2.y, 0.f));
            }
            const uint32_t bpo = (ks * 4 + qpos) * 8;
            #pragma unroll
            for (int nt = 0; nt < 8; nt++) {
                float2 bv = *(const float2*)(sm + (ws - sb) +
                                             (wn * 64 + nt * 8 + qid) * WS_STRIDE + bpo);
                uint32_t b0 = __float_as_uint(bv.x);
                uint32_t b1 = __float_as_uint(bv.y);
                #pragma unroll
                for (int t = 0; t < 2; t++)
                    mma_tf32(acc[t][nt], a[t], b0, b1);
            }
        }

        if (c + 1 < NCH) {
            cp_wait0();          // W(c+1) arrived
            __syncthreads();     // all warps done with MMA(c); stage s reusable
        }
    }

    // ---------------- epilogue ----------------
    const float* w3s = (const float*)(sm + W3_OFF);
    float* logp = (float*)(sm + LOG_OFF);
    const int j_g = jt * 8 + qid;

    #pragma unroll
    for (int t = 0; t < 2; t++) {
        #pragma unroll
        for (int half = 0; half < 2; half++) {
            const int i_g = it * 16 + wm * 4 + t * 2 + half;
            float* orow = out + (size_t)((b * NTOK + i_g) * NTOK + j_g) * OUTC
                        + m * 258 + wn * 64;
            float l0 = 0.f, l1 = 0.f;
            #pragma unroll
            for (int nt = 0; nt < 8; nt++) {
                float d0 = fmaxf(acc[t][nt][half * 2],     0.f);
                float d1 = fmaxf(acc[t][nt][half * 2 + 1], 0.f);
                int nn = nt * 8 + qpos * 2;
                float4 wv = *(const float4*)(w3s + (wn * 64 + nn) * 2);
                l0 = fmaf(d0, wv.x, fmaf(d1, wv.z, l0));
                l1 = fmaf(d0, wv.y, fmaf(d1, wv.w, l1));
                *(float2*)(orow + nn) = make_float2(d0, d1);
            }
            // reduce over qpos (4 lanes sharing a row)
            l0 += __shfl_xor_sync(0xffffffffu, l0, 1);
            l1 += __shfl_xor_sync(0xffffffffu, l1, 1);
            l0 += __shfl_xor_sync(0xffffffffu, l0, 2);
            l1 += __shfl_xor_sync(0xffffffffu, l1, 2);
            if (qpos == 0) {
                int r_cta = wm * 32 + t * 16 + half * 8 + qid;
                *(float2*)(logp + r_cta * 8 + wn * 2) = make_float2(l0, l1);
            }
        }
    }
    __syncthreads();

    if (tid < 128) {
        float l0 = 0.f, l1 = 0.f;
        #pragma unroll
        for (int w = 0; w < 4; w++) {
            float2 p = *(const float2*)(logp + tid * 8 + w * 2);
            l0 += p.x; l1 += p.y;
        }
        float mx = fmaxf(l0, l1);
        float e0 = __expf(l0 - mx), e1 = __expf(l1 - mx);
        float inv = 1.f / (e0 + e1);
        const int i_g = it * 16 + (tid >> 3);
        const int jg2 = jt * 8 + (tid & 7);
        float* orow = out + (size_t)((b * NTOK + i_g) * NTOK + jg2) * OUTC + m * 258;
        *(float2*)(orow + 256) = make_float2(e0 * inv, e1 * inv);
    }
}

// ---------------------------------------------------------------------------
extern "C" void kernel_launch(void* const* d_in, const int* in_sizes, int n_in,
                              void* d_out, int out_size) {
    (void)in_sizes; (void)n_in; (void)out_size;
    const float* P    = (const float*)d_in[0];
    const float* Wf1  = (const float*)d_in[1];
    const float* Wf2  = (const float*)d_in[2];
    const float* w3   = (const float*)d_in[3];
    const float* Wh1a = (const float*)d_in[4];
    const float* Wh1b = (const float*)d_in[5];
    const float* wl1  = (const float*)d_in[6];
    const float* Wh2a = (const float*)d_in[7];
    const float* Wh2b = (const float*)d_in[8];
    const float* wl2  = (const float*)d_in[9];
    float* out = (float*)d_out;

    cudaFuncSetAttribute(pair_mma,
                         cudaFuncAttributeMaxDynamicSharedMemorySize,
                         SMEM_TOTAL);

    w2_pack<<<dim3(NCH, 3), 256>>>(Wf2, Wh1b, Wh2b);
    uv_gemm<<<dim3(96, 8), 256>>>(P, Wf1, Wh1a, Wh2a);
    pair_mma<<<dim3(16, 8, 12), 512, SMEM_TOTAL>>>(w3, wl1, wl2, out);
}